// round 7
// baseline (speedup 1.0000x reference)
#include <cuda_runtime.h>
#include <mma.h>
#include <cstdint>

#define NODES 50000
#define CE    64
#define CN    256
#define COUT  256
#define KSTEP 32
#define NKS   10   // 320 / 32
#define STAGES 3

#define AS_LD   36                    // 32 + 4 pad
#define BS_LD   264                   // 256 + 8 pad
#define AS_STAGE (128 * AS_LD)
#define BS_STAGE (32 * BS_LD)
#define SMEM_FLOATS (STAGES * AS_STAGE + STAGES * BS_STAGE)
#define SMEM_BYTES  (SMEM_FLOATS * 4) // 156,672 B

// scratch: accumulator (scaled in-place after scatter) + invD
__device__ float g_A[(size_t)NODES * CE];
__device__ float g_invD[NODES];

// ---------------------------------------------------------------------------
// cp.async helpers
// ---------------------------------------------------------------------------
__device__ __forceinline__ void cp_async16(void* smem, const void* gsrc, bool pred) {
    uint32_t s = (uint32_t)__cvta_generic_to_shared(smem);
    int sz = pred ? 16 : 0;
    asm volatile("cp.async.cg.shared.global [%0], [%1], 16, %2;\n"
                 :: "r"(s), "l"(gsrc), "r"(sz));
}
#define CP_COMMIT() asm volatile("cp.async.commit_group;\n" ::: "memory")
#define CP_WAIT(n)  asm volatile("cp.async.wait_group %0;\n" :: "n"(n) : "memory")

// ---------------------------------------------------------------------------
// Kernel 1: zero accumulator + precompute invD
// ---------------------------------------------------------------------------
__global__ void zero_kernel(const float* __restrict__ D) {
    int i = blockIdx.x * blockDim.x + threadIdx.x;
    if (i < NODES) g_invD[i] = __frcp_rn(__ldg(D + i));
    if (i < NODES * CE / 4)
        reinterpret_cast<float4*>(g_A)[i] = make_float4(0.f, 0.f, 0.f, 0.f);
}

// ---------------------------------------------------------------------------
// Kernel 2: edge scatter via bulk-async reduce.
//   Batch of 32 edges: cp.async 8KB into smem, then warp 0's lanes each issue
//   one cp.reduce.async.bulk (256B, f32 add) to g_A[row].  Double-buffered;
//   reuse guarded by cp.async.bulk.wait_group.read.
// ---------------------------------------------------------------------------
__global__ __launch_bounds__(256)
void scatter_bulk_kernel(const float4* __restrict__ ea,
                         const int* __restrict__ row_idx, int E) {
    __shared__ float4 buf[2][512];   // 2 x 8 KB
    const int tid  = threadIdx.x;
    const int warp = tid >> 5;
    const int lane = tid & 31;
    const int nb   = (E + 31) >> 5;

    int kk = 0;
    for (int k = blockIdx.x; k < nb; k += gridDim.x, kk++) {
        const int b = kk & 1;
        // bulk reads from buf[b] were committed 2 local iters ago -> allow 1
        // outstanding group (last iter's), require older ones read-complete.
        if (warp == 0)
            asm volatile("cp.async.bulk.wait_group.read 1;" ::: "memory");
        __syncthreads();

        const int e0 = k << 5;
        // fill 32 edge rows (512 float4), fully coalesced
#pragma unroll
        for (int i = 0; i < 2; i++) {
            int idx = tid + (i << 8);
            bool ok = (e0 + (idx >> 4)) < E;
            cp_async16(&buf[b][idx], ea + ((size_t)e0 * 16 + idx), ok);
        }
        CP_COMMIT();
        CP_WAIT(0);
        __syncthreads();

        if (warp == 0) {
            asm volatile("fence.proxy.async.shared::cta;" ::: "memory");
            int e = e0 + lane;
            if (e < E) {
                int r = __ldg(row_idx + e);
                float* dst = g_A + (size_t)r * CE;
                uint32_t s = (uint32_t)__cvta_generic_to_shared(&buf[b][lane * 16]);
                asm volatile(
                    "cp.reduce.async.bulk.global.shared::cta.bulk_group.add.f32 "
                    "[%0], [%1], %2;"
                    :: "l"(dst), "r"(s), "r"(256) : "memory");
            }
            asm volatile("cp.async.bulk.commit_group;" ::: "memory");
        }
    }
    if (warp == 0)
        asm volatile("cp.async.bulk.wait_group 0;" ::: "memory");
}

// ---------------------------------------------------------------------------
// Kernel 2b: in-place scale g_A by invD[row]  (25.6 MB traffic, ~5us)
// ---------------------------------------------------------------------------
__global__ void scale_kernel() {
    int i = blockIdx.x * blockDim.x + threadIdx.x;
    const int n4 = NODES * CE / 4;
    if (i < n4) {
        float s = g_invD[i >> 4];
        float4 v = reinterpret_cast<float4*>(g_A)[i];
        v.x *= s; v.y *= s; v.z *= s; v.w *= s;
        reinterpret_cast<float4*>(g_A)[i] = v;
    }
}

// ---------------------------------------------------------------------------
// Kernel 3: fused GEMM  out = relu([A/D | X] @ [W_pass; W_self] + bias)
//   (unchanged from R6: CTA 128x256, KSTEP=32, 3-stage, 1 sync/iter)
// ---------------------------------------------------------------------------
using namespace nvcuda;

__device__ __forceinline__ void load_stage(
    float* As, float* Bs, int ks, int row0, int nNodes,
    const float* __restrict__ X, const float* __restrict__ Wp,
    const float* __restrict__ Ws, int tid)
{
    const int k0 = ks * KSTEP;
#pragma unroll
    for (int i = 0; i < 2; i++) {
        int j  = tid + i * 512;
        int r  = j >> 3, c4 = (j & 7) * 4;
        int gr = row0 + r;
        bool ok = gr < nNodes;
        int grc = ok ? gr : 0;
        const float* src = (k0 < 64)
            ? (g_A + (size_t)grc * CE + (k0 + c4))
            : (X   + (size_t)grc * CN + (k0 - 64 + c4));
        cp_async16(As + r * AS_LD + c4, src, ok);
    }
#pragma unroll
    for (int i = 0; i < 4; i++) {
        int j = tid + i * 512;
        int r = j >> 6, c4 = (j & 63) * 4;
        int k = k0 + r;
        const float* src = (k < 64)
            ? (Wp + (size_t)k * COUT + c4)
            : (Ws + (size_t)(k - 64) * COUT + c4);
        cp_async16(Bs + r * BS_LD + c4, src, true);
    }
}

__global__ __launch_bounds__(512, 1)
void gemm_kernel(const float* __restrict__ X,
                 const float* __restrict__ Wp, const float* __restrict__ bp,
                 const float* __restrict__ Ws, const float* __restrict__ bs,
                 float* __restrict__ out, int nNodes) {
    extern __shared__ float smem[];
    float* AsBase = smem;
    float* BsBase = smem + STAGES * AS_STAGE;

    const int tid  = threadIdx.x;
    const int warp = tid >> 5;
    const int wm   = warp >> 2;
    const int wn   = warp & 3;
    const int row0 = blockIdx.x * 128;

    for (int i = tid; i < 16 * 256; i += 512) {
        int r = i >> 8, c = i & 255;
        BsBase[r * BS_LD + c] = __ldg(bp + c) + __ldg(bs + c);
    }
    __syncthreads();

    wmma::fragment<wmma::accumulator, 16, 16, 8, float> acc[2][4];
#pragma unroll
    for (int mi = 0; mi < 2; mi++)
#pragma unroll
        for (int ni = 0; ni < 4; ni++)
            wmma::load_matrix_sync(acc[mi][ni], BsBase + wn * 64 + ni * 16,
                                   BS_LD, wmma::mem_row_major);
    __syncthreads();

#pragma unroll
    for (int s = 0; s < STAGES - 1; s++) {
        load_stage(AsBase + s * AS_STAGE, BsBase + s * BS_STAGE, s,
                   row0, nNodes, X, Wp, Ws, tid);
        CP_COMMIT();
    }

    for (int ks = 0; ks < NKS; ks++) {
        const int cbuf = ks % STAGES;
        float* As = AsBase + cbuf * AS_STAGE;
        float* Bs = BsBase + cbuf * BS_STAGE;

        if (ks < NKS - 1) { CP_WAIT(1); } else { CP_WAIT(0); }
        __syncthreads();

        if (ks + STAGES - 1 < NKS) {
            const int wbuf = (ks + STAGES - 1) % STAGES;
            load_stage(AsBase + wbuf * AS_STAGE, BsBase + wbuf * BS_STAGE,
                       ks + STAGES - 1, row0, nNodes, X, Wp, Ws, tid);
            CP_COMMIT();
        }

#pragma unroll
        for (int kk8 = 0; kk8 < 4; kk8++) {
            wmma::fragment<wmma::matrix_a, 16, 16, 8, wmma::precision::tf32,
                           wmma::row_major> af[2];
            wmma::fragment<wmma::matrix_b, 16, 16, 8, wmma::precision::tf32,
                           wmma::row_major> bf[4];
#pragma unroll
            for (int mi = 0; mi < 2; mi++) {
                wmma::load_matrix_sync(af[mi],
                    As + (wm * 32 + mi * 16) * AS_LD + kk8 * 8, AS_LD);
#pragma unroll
                for (int t = 0; t < af[mi].num_elements; t++)
                    af[mi].x[t] = wmma::__float_to_tf32(af[mi].x[t]);
            }
#pragma unroll
            for (int ni = 0; ni < 4; ni++) {
                wmma::load_matrix_sync(bf[ni],
                    Bs + (kk8 * 8) * BS_LD + wn * 64 + ni * 16, BS_LD);
#pragma unroll
                for (int t = 0; t < bf[ni].num_elements; t++)
                    bf[ni].x[t] = wmma::__float_to_tf32(bf[ni].x[t]);
            }
#pragma unroll
            for (int mi = 0; mi < 2; mi++)
#pragma unroll
                for (int ni = 0; ni < 4; ni++)
                    wmma::mma_sync(acc[mi][ni], af[mi], bf[ni], acc[mi][ni]);
        }
    }

#pragma unroll
    for (int mi = 0; mi < 2; mi++)
#pragma unroll
        for (int ni = 0; ni < 4; ni++)
#pragma unroll
            for (int t = 0; t < acc[mi][ni].num_elements; t++)
                acc[mi][ni].x[t] = fmaxf(acc[mi][ni].x[t], 0.f);

    __syncthreads();

    if (row0 + 128 <= nNodes) {
#pragma unroll
        for (int mi = 0; mi < 2; mi++)
#pragma unroll
            for (int ni = 0; ni < 4; ni++)
                wmma::store_matrix_sync(
                    out + (size_t)(row0 + wm * 32 + mi * 16) * COUT
                        + wn * 64 + ni * 16,
                    acc[mi][ni], COUT, wmma::mem_row_major);
    } else {
        float* stg = smem;
        for (int chunk = 0; chunk < 4; chunk++) {
            __syncthreads();
            if (wm == chunk) {
#pragma unroll
                for (int mi = 0; mi < 2; mi++)
#pragma unroll
                    for (int ni = 0; ni < 4; ni++)
                        wmma::store_matrix_sync(
                            stg + (mi * 16) * BS_LD + wn * 64 + ni * 16,
                            acc[mi][ni], BS_LD, wmma::mem_row_major);
            }
            __syncthreads();
            int base = row0 + chunk * 32;
            for (int idx = tid; idx < 32 * 256; idx += 512) {
                int r = idx >> 8, c = idx & 255;
                int gr = base + r;
                if (gr < nNodes)
                    out[(size_t)gr * COUT + c] = stg[r * BS_LD + c];
            }
        }
    }
}

// ---------------------------------------------------------------------------
extern "C" void kernel_launch(void* const* d_in, const int* in_sizes, int n_in,
                              void* d_out, int out_size) {
    const float*  D   = (const float*)d_in[0];
    const int*    row = (const int*)d_in[1];
    const float4* ea  = (const float4*)d_in[2];
    const float*  X   = (const float*)d_in[3];
    const float*  Wp  = (const float*)d_in[4];
    const float*  bp  = (const float*)d_in[5];
    const float*  Ws  = (const float*)d_in[6];
    const float*  bs  = (const float*)d_in[7];
    float* out = (float*)d_out;

    const int nNodes = in_sizes[0];
    const int E      = in_sizes[1];

    static bool attr_set = false;
    if (!attr_set) {
        cudaFuncSetAttribute(gemm_kernel,
                             cudaFuncAttributeMaxDynamicSharedMemorySize,
                             SMEM_BYTES);
        attr_set = true;
    }

    // 1) zero accumulator + invD
    {
        int n4 = NODES * CE / 4;
        zero_kernel<<<(n4 + 255) / 256, 256>>>(D);
    }
    // 2) scatter edges via bulk-async reduce
    {
        int nb = (E + 31) / 32;
        int grid = nb < 1184 ? nb : 1184;   // 148 SMs x 8 CTAs
        scatter_bulk_kernel<<<grid, 256>>>(ea, row, E);
    }
    // 2b) in-place scale by invD
    {
        int n4 = NODES * CE / 4;
        scale_kernel<<<(n4 + 255) / 256, 256>>>();
    }
    // 3) fused GEMM + bias + ReLU
    {
        int grid = (nNodes + 127) / 128;
        gemm_kernel<<<grid, 512, SMEM_BYTES>>>(X, Wp, bp, Ws, bs, out, nNodes);
    }
}

// round 9
// speedup vs baseline: 1.0932x; 1.0932x over previous
#include <cuda_runtime.h>
#include <mma.h>
#include <cstdint>

#define NODES 50000
#define CE    64
#define CN    256
#define COUT  256
#define KSTEP 32
#define NKS   10   // 320 / 32
#define STAGES 3

#define AS_LD   36                    // 32 + 4 pad
#define BS_LD   264                   // 256 + 8 pad
#define AS_STAGE (128 * AS_LD)
#define BS_STAGE (32 * BS_LD)
#define SMEM_FLOATS (STAGES * AS_STAGE + STAGES * BS_STAGE)
#define SMEM_BYTES  (SMEM_FLOATS * 4) // 156,672 B

// __device__ scratch
__device__ float g_A[(size_t)NODES * CE];      // pre-scaled A/D
__device__ float g_invD[NODES];
__device__ float g_Bt[NKS * 32 * 256];         // [chunk][k][n], tf32-rounded

// ---------------------------------------------------------------------------
// cp.async helpers
// ---------------------------------------------------------------------------
__device__ __forceinline__ void cp_async16(void* smem, const void* gsrc, bool pred) {
    uint32_t s = (uint32_t)__cvta_generic_to_shared(smem);
    int sz = pred ? 16 : 0;
    asm volatile("cp.async.cg.shared.global [%0], [%1], 16, %2;\n"
                 :: "r"(s), "l"(gsrc), "r"(sz));
}
#define CP_COMMIT() asm volatile("cp.async.commit_group;\n" ::: "memory")
#define CP_WAIT(n)  asm volatile("cp.async.wait_group %0;\n" :: "n"(n) : "memory")

// ---------------------------------------------------------------------------
// Kernel 1: zero accumulator + precompute invD
// ---------------------------------------------------------------------------
__global__ void zero_kernel(const float* __restrict__ D) {
    int i = blockIdx.x * blockDim.x + threadIdx.x;
    if (i < NODES) g_invD[i] = __frcp_rn(__ldg(D + i));
    if (i < NODES * CE / 4)
        reinterpret_cast<float4*>(g_A)[i] = make_float4(0.f, 0.f, 0.f, 0.f);
}

// ---------------------------------------------------------------------------
// Kernel 1b: build tf32-rounded, chunked weight image g_Bt[kc][kk][n]
// ---------------------------------------------------------------------------
__global__ void wtrans_kernel(const float* __restrict__ Wp,
                              const float* __restrict__ Ws) {
    int idx = blockIdx.x * 256 + threadIdx.x;
    if (idx >= NKS * 32 * 256) return;
    int kc = idx >> 13;            // /8192
    int kk = (idx >> 8) & 31;
    int n  = idx & 255;
    int k  = kc * 32 + kk;
    float v = (k < 64) ? __ldg(Wp + k * COUT + n)
                       : __ldg(Ws + (size_t)(k - 64) * COUT + n);
    float o;
    asm("cvt.rna.tf32.f32 %0, %1;" : "=f"(o) : "f"(v));
    g_Bt[idx] = o;
}

// ---------------------------------------------------------------------------
// Kernel 2: edge scatter (R4, best measured): red.v4 pre-scaled by invD
// ---------------------------------------------------------------------------
__global__ void scatter_kernel(const float4* __restrict__ ea,
                               const int* __restrict__ row_idx, int total16) {
    int i = blockIdx.x * 256 + threadIdx.x;
    if (i >= total16) return;
    int e = i >> 4, t = i & 15;
    int r = __ldg(row_idx + e);
    float s = __ldg(g_invD + r);
    float4 v = __ldg(ea + i);
    v.x *= s; v.y *= s; v.z *= s; v.w *= s;
    float* dst = g_A + (size_t)r * CE + t * 4;
    asm volatile("red.global.add.v4.f32 [%0], {%1, %2, %3, %4};"
                 :: "l"(dst), "f"(v.x), "f"(v.y), "f"(v.z), "f"(v.w) : "memory");
}

// ---------------------------------------------------------------------------
// Kernel 3: fused GEMM  out = relu([A/D | X] @ [Wp;Ws] + bias)
//   CTA 128x256, KSTEP=32, 3-stage cp.async, 1 sync/iter, 512 threads,
//   fragment double-buffering, B pre-converted to tf32 (no B cvt in loop).
// ---------------------------------------------------------------------------
using namespace nvcuda;

typedef wmma::fragment<wmma::matrix_a, 16, 16, 8, wmma::precision::tf32,
                       wmma::row_major> AFrag;
typedef wmma::fragment<wmma::matrix_b, 16, 16, 8, wmma::precision::tf32,
                       wmma::row_major> BFrag;

__device__ __forceinline__ void load_frags(
    AFrag (&af)[2], BFrag (&bf)[4],
    const float* As, const float* Bs, int kk8, int wm, int wn)
{
#pragma unroll
    for (int mi = 0; mi < 2; mi++) {
        wmma::load_matrix_sync(af[mi],
            As + (wm * 32 + mi * 16) * AS_LD + kk8 * 8, AS_LD);
#pragma unroll
        for (int t = 0; t < af[mi].num_elements; t++)
            af[mi].x[t] = wmma::__float_to_tf32(af[mi].x[t]);
    }
#pragma unroll
    for (int ni = 0; ni < 4; ni++)
        wmma::load_matrix_sync(bf[ni],
            Bs + (kk8 * 8) * BS_LD + wn * 64 + ni * 16, BS_LD);
    // B already tf32-rounded in g_Bt: no cvt
}

__device__ __forceinline__ void load_stage(
    float* As, float* Bs, int ks, int row0, int nNodes,
    const float* __restrict__ X, int tid)
{
    const int k0 = ks * KSTEP;
    // As: 128 rows x 32 k  (1024 float4, 2 per thread)
#pragma unroll
    for (int i = 0; i < 2; i++) {
        int j  = tid + i * 512;
        int r  = j >> 3, c4 = (j & 7) * 4;
        int gr = row0 + r;
        bool ok = gr < nNodes;
        int grc = ok ? gr : 0;
        const float* src = (k0 < 64)
            ? (g_A + (size_t)grc * CE + (k0 + c4))
            : (X   + (size_t)grc * CN + (k0 - 64 + c4));
        cp_async16(As + r * AS_LD + c4, src, ok);
    }
    // Bs: 32 k-rows x 256 cols, contiguous from g_Bt chunk (2048 f4, 4/thread)
    const float* bsrc = g_Bt + ks * (32 * 256);
#pragma unroll
    for (int i = 0; i < 4; i++) {
        int j = tid + i * 512;
        int r = j >> 6, c4 = (j & 63) * 4;
        cp_async16(Bs + r * BS_LD + c4, bsrc + r * 256 + c4, true);
    }
}

__global__ __launch_bounds__(512, 1)
void gemm_kernel(const float* __restrict__ X,
                 const float* __restrict__ bp, const float* __restrict__ bs,
                 float* __restrict__ out, int nNodes) {
    extern __shared__ float smem[];
    float* AsBase = smem;
    float* BsBase = smem + STAGES * AS_STAGE;

    const int tid  = threadIdx.x;
    const int warp = tid >> 5;
    const int wm   = warp >> 2;        // 0..3, 32 rows each
    const int wn   = warp & 3;         // 0..3, 64 cols each
    const int row0 = blockIdx.x * 128;

    // bias (b_pass + b_self) via Bs stage 0
    for (int i = tid; i < 16 * 256; i += 512) {
        int r = i >> 8, c = i & 255;
        BsBase[r * BS_LD + c] = __ldg(bp + c) + __ldg(bs + c);
    }
    __syncthreads();

    wmma::fragment<wmma::accumulator, 16, 16, 8, float> acc[2][4];
#pragma unroll
    for (int mi = 0; mi < 2; mi++)
#pragma unroll
        for (int ni = 0; ni < 4; ni++)
            wmma::load_matrix_sync(acc[mi][ni], BsBase + wn * 64 + ni * 16,
                                   BS_LD, wmma::mem_row_major);
    __syncthreads();

    // prologue: fill stages 0..STAGES-2
#pragma unroll
    for (int s = 0; s < STAGES - 1; s++) {
        load_stage(AsBase + s * AS_STAGE, BsBase + s * BS_STAGE, s,
                   row0, nNodes, X, tid);
        CP_COMMIT();
    }

    AFrag af[2][2];
    BFrag bf[2][4];

    for (int ks = 0; ks < NKS; ks++) {
        const int cbuf = ks % STAGES;
        const float* As = AsBase + cbuf * AS_STAGE;
        const float* Bs = BsBase + cbuf * BS_STAGE;

        if (ks < NKS - 1) { CP_WAIT(1); } else { CP_WAIT(0); }
        __syncthreads();   // also: compute(ks-1) drained -> its buf reusable

        if (ks + STAGES - 1 < NKS) {
            const int wbuf = (ks + STAGES - 1) % STAGES;
            load_stage(AsBase + wbuf * AS_STAGE, BsBase + wbuf * BS_STAGE,
                       ks + STAGES - 1, row0, nNodes, X, tid);
            CP_COMMIT();
        }

        // fragment-level software pipeline over the 4 k8-steps
        load_frags(af[0], bf[0], As, Bs, 0, wm, wn);
#pragma unroll
        for (int kk8 = 0; kk8 < 4; kk8++) {
            const int cur = kk8 & 1;
            if (kk8 < 3)
                load_frags(af[cur ^ 1], bf[cur ^ 1], As, Bs, kk8 + 1, wm, wn);
#pragma unroll
            for (int mi = 0; mi < 2; mi++)
#pragma unroll
                for (int ni = 0; ni < 4; ni++)
                    wmma::mma_sync(acc[mi][ni], af[cur][mi], bf[cur][ni],
                                   acc[mi][ni]);
        }
    }

    // ReLU
#pragma unroll
    for (int mi = 0; mi < 2; mi++)
#pragma unroll
        for (int ni = 0; ni < 4; ni++)
#pragma unroll
            for (int t = 0; t < acc[mi][ni].num_elements; t++)
                acc[mi][ni].x[t] = fmaxf(acc[mi][ni].x[t], 0.f);

    __syncthreads();

    if (row0 + 128 <= nNodes) {
#pragma unroll
        for (int mi = 0; mi < 2; mi++)
#pragma unroll
            for (int ni = 0; ni < 4; ni++)
                wmma::store_matrix_sync(
                    out + (size_t)(row0 + wm * 32 + mi * 16) * COUT
                        + wn * 64 + ni * 16,
                    acc[mi][ni], COUT, wmma::mem_row_major);
    } else {
        float* stg = smem;
        for (int chunk = 0; chunk < 4; chunk++) {
            __syncthreads();
            if (wm == chunk) {
#pragma unroll
                for (int mi = 0; mi < 2; mi++)
#pragma unroll
                    for (int ni = 0; ni < 4; ni++)
                        wmma::store_matrix_sync(
                            stg + (mi * 16) * BS_LD + wn * 64 + ni * 16,
                            acc[mi][ni], BS_LD, wmma::mem_row_major);
            }
            __syncthreads();
            int base = row0 + chunk * 32;
            for (int idx = tid; idx < 32 * 256; idx += 512) {
                int r = idx >> 8, c = idx & 255;
                int gr = base + r;
                if (gr < nNodes)
                    out[(size_t)gr * COUT + c] = stg[r * BS_LD + c];
            }
        }
    }
}

// ---------------------------------------------------------------------------
extern "C" void kernel_launch(void* const* d_in, const int* in_sizes, int n_in,
                              void* d_out, int out_size) {
    const float*  D   = (const float*)d_in[0];
    const int*    row = (const int*)d_in[1];
    const float4* ea  = (const float4*)d_in[2];
    const float*  X   = (const float*)d_in[3];
    const float*  Wp  = (const float*)d_in[4];
    const float*  bp  = (const float*)d_in[5];
    const float*  Ws  = (const float*)d_in[6];
    const float*  bs  = (const float*)d_in[7];
    float* out = (float*)d_out;

    const int nNodes = in_sizes[0];
    const int E      = in_sizes[1];

    static bool attr_set = false;
    if (!attr_set) {
        cudaFuncSetAttribute(gemm_kernel,
                             cudaFuncAttributeMaxDynamicSharedMemorySize,
                             SMEM_BYTES);
        attr_set = true;
    }

    {   // zero + invD
        int n4 = NODES * CE / 4;
        zero_kernel<<<(n4 + 255) / 256, 256>>>(D);
    }
    {   // tf32-rounded chunked weights
        int n = NKS * 32 * 256;
        wtrans_kernel<<<(n + 255) / 256, 256>>>(Wp, Ws);
    }
    {   // scatter
        int total16 = E * 16;
        scatter_kernel<<<(total16 + 255) / 256, 256>>>(ea, row, total16);
    }
    {   // GEMM
        int grid = (nNodes + 127) / 128;
        gemm_kernel<<<grid, 512, SMEM_BYTES>>>(X, bp, bs, out, nNodes);
    }
}

// round 10
// speedup vs baseline: 1.4949x; 1.3675x over previous
#include <cuda_runtime.h>
#include <cuda_fp16.h>
#include <mma.h>
#include <cstdint>

#define NODES 50000
#define CE    64
#define CN    256
#define KTOT  320
#define COUT  256
#define KSTEP 32
#define NKS   10   // 320 / 32
#define STAGES 3

#define AS_LD   40                     // halves: 32 + 8 pad
#define BS_LD   264                    // halves: 256 + 8 pad
#define AS_STAGE (128 * AS_LD)         // halves per A stage
#define BS_STAGE (32 * BS_LD)          // halves per B stage
#define SMEM_BYTES ((STAGES * AS_STAGE + STAGES * BS_STAGE) * 2)  // 81,408 B

// __device__ scratch
__device__ float  g_A[(size_t)NODES * CE];        // fp32 atomic accumulator (A/D)
__device__ float  g_invD[NODES];
__device__ __half g_Ah[(size_t)NODES * KTOT];     // half [A/D | X]
__device__ __half g_Bh[KTOT * COUT];              // half weights, k-major

// ---------------------------------------------------------------------------
// cp.async helpers
// ---------------------------------------------------------------------------
__device__ __forceinline__ void cp_async16(void* smem, const void* gsrc, bool pred) {
    uint32_t s = (uint32_t)__cvta_generic_to_shared(smem);
    int sz = pred ? 16 : 0;
    asm volatile("cp.async.cg.shared.global [%0], [%1], 16, %2;\n"
                 :: "r"(s), "l"(gsrc), "r"(sz));
}
#define CP_COMMIT() asm volatile("cp.async.commit_group;\n" ::: "memory")
#define CP_WAIT(n)  asm volatile("cp.async.wait_group %0;\n" :: "n"(n) : "memory")

// ---------------------------------------------------------------------------
// 1) zero accumulator + invD
// ---------------------------------------------------------------------------
__global__ void zero_kernel(const float* __restrict__ D) {
    int i = blockIdx.x * blockDim.x + threadIdx.x;
    if (i < NODES) g_invD[i] = __frcp_rn(__ldg(D + i));
    if (i < NODES * CE / 4)
        reinterpret_cast<float4*>(g_A)[i] = make_float4(0.f, 0.f, 0.f, 0.f);
}

// 1b) weights -> half, k-major g_Bh[k][n]
__global__ void wtrans_kernel(const float* __restrict__ Wp,
                              const float* __restrict__ Ws) {
    int idx = blockIdx.x * 256 + threadIdx.x;
    if (idx >= KTOT * COUT) return;
    int k = idx >> 8, n = idx & 255;
    float v = (k < 64) ? __ldg(Wp + k * COUT + n)
                       : __ldg(Ws + (size_t)(k - 64) * COUT + n);
    g_Bh[idx] = __float2half_rn(v);
}

// 1c) X -> half into g_Ah columns [64, 320)
__global__ void convx_kernel(const float* __restrict__ X) {
    int i = blockIdx.x * blockDim.x + threadIdx.x;   // half2 index
    const int tot = NODES * CN / 2;
    if (i >= tot) return;
    int n = i / (CN / 2), c2 = i % (CN / 2);
    float2 v = *reinterpret_cast<const float2*>(X + (size_t)n * CN + c2 * 2);
    *reinterpret_cast<__half2*>(g_Ah + (size_t)n * KTOT + 64 + c2 * 2) =
        __floats2half2_rn(v.x, v.y);
}

// ---------------------------------------------------------------------------
// 2) edge scatter (R4, best measured)
// ---------------------------------------------------------------------------
__global__ void scatter_kernel(const float4* __restrict__ ea,
                               const int* __restrict__ row_idx, int total16) {
    int i = blockIdx.x * 256 + threadIdx.x;
    if (i >= total16) return;
    int e = i >> 4, t = i & 15;
    int r = __ldg(row_idx + e);
    float s = __ldg(g_invD + r);
    float4 v = __ldg(ea + i);
    v.x *= s; v.y *= s; v.z *= s; v.w *= s;
    float* dst = g_A + (size_t)r * CE + t * 4;
    asm volatile("red.global.add.v4.f32 [%0], {%1, %2, %3, %4};"
                 :: "l"(dst), "f"(v.x), "f"(v.y), "f"(v.z), "f"(v.w) : "memory");
}

// 2b) A/D -> half into g_Ah columns [0, 64)
__global__ void conva_kernel() {
    int i = blockIdx.x * blockDim.x + threadIdx.x;   // half2 index
    const int tot = NODES * CE / 2;
    if (i >= tot) return;
    int n = i >> 5, c2 = i & 31;
    float2 v = *reinterpret_cast<const float2*>(g_A + (size_t)n * CE + c2 * 2);
    *reinterpret_cast<__half2*>(g_Ah + (size_t)n * KTOT + c2 * 2) =
        __floats2half2_rn(v.x, v.y);
}

// ---------------------------------------------------------------------------
// 3) fp16 GEMM  out = relu(g_Ah @ g_Bh + bias)
//    CTA 128x256, KSTEP=32, 3-stage cp.async, 1 sync/iter, 512 threads.
// ---------------------------------------------------------------------------
using namespace nvcuda;

__device__ __forceinline__ void load_stage(
    __half* As, __half* Bs, int ks, int row0, int nNodes, int tid)
{
    const int k0 = ks * KSTEP;
    // A: 128 rows x 32 halves (64B/row) -> 512 x 16B, 1 per thread
    {
        int r  = tid >> 2, c8 = (tid & 3) * 8;
        int gr = row0 + r;
        bool ok = gr < nNodes;
        int grc = ok ? gr : 0;
        cp_async16(As + r * AS_LD + c8,
                   g_Ah + (size_t)grc * KTOT + k0 + c8, ok);
    }
    // B: 32 rows x 256 halves (512B/row) -> 1024 x 16B, 2 per thread
    const __half* bsrc = g_Bh + (size_t)k0 * COUT;
#pragma unroll
    for (int i = 0; i < 2; i++) {
        int j = tid + i * 512;
        int r = j >> 5, c8 = (j & 31) * 8;
        cp_async16(Bs + r * BS_LD + c8, bsrc + r * COUT + c8, true);
    }
}

typedef wmma::fragment<wmma::matrix_a, 16, 16, 16, __half, wmma::row_major> AFrag;
typedef wmma::fragment<wmma::matrix_b, 16, 16, 16, __half, wmma::row_major> BFrag;

__global__ __launch_bounds__(512, 1)
void gemm_kernel(const float* __restrict__ bp, const float* __restrict__ bs,
                 float* __restrict__ out, int nNodes) {
    extern __shared__ __half smem[];
    __half* AsBase = smem;
    __half* BsBase = smem + STAGES * AS_STAGE;

    const int tid  = threadIdx.x;
    const int warp = tid >> 5;
    const int wm   = warp >> 2;        // 0..3, 32 rows each
    const int wn   = warp & 3;         // 0..3, 64 cols each
    const int row0 = blockIdx.x * 128;

    // ---- bias preload via float view of smem (overwritten later) ----
    float* biasf = reinterpret_cast<float*>(smem);   // 16 x 264 floats
    for (int i = tid; i < 16 * 256; i += 512) {
        int r = i >> 8, c = i & 255;
        biasf[r * 264 + c] = __ldg(bp + c) + __ldg(bs + c);
    }
    __syncthreads();

    wmma::fragment<wmma::accumulator, 16, 16, 16, float> acc[2][4];
#pragma unroll
    for (int mi = 0; mi < 2; mi++)
#pragma unroll
        for (int ni = 0; ni < 4; ni++)
            wmma::load_matrix_sync(acc[mi][ni], biasf + wn * 64 + ni * 16,
                                   264, wmma::mem_row_major);
    __syncthreads();

    // ---- prologue: fill stages 0..STAGES-2 ----
#pragma unroll
    for (int s = 0; s < STAGES - 1; s++) {
        load_stage(AsBase + s * AS_STAGE, BsBase + s * BS_STAGE, s,
                   row0, nNodes, tid);
        CP_COMMIT();
    }

    for (int ks = 0; ks < NKS; ks++) {
        const int cbuf = ks % STAGES;
        const __half* As = AsBase + cbuf * AS_STAGE;
        const __half* Bs = BsBase + cbuf * BS_STAGE;

        if (ks < NKS - 1) { CP_WAIT(1); } else { CP_WAIT(0); }
        __syncthreads();   // compute(ks-1) drained -> its buffer reusable

        if (ks + STAGES - 1 < NKS) {
            const int wbuf = (ks + STAGES - 1) % STAGES;
            load_stage(AsBase + wbuf * AS_STAGE, BsBase + wbuf * BS_STAGE,
                       ks + STAGES - 1, row0, nNodes, tid);
            CP_COMMIT();
        }

#pragma unroll
        for (int k16 = 0; k16 < 2; k16++) {
            AFrag af[2];
            BFrag bf[4];
#pragma unroll
            for (int mi = 0; mi < 2; mi++)
                wmma::load_matrix_sync(af[mi],
                    As + (wm * 32 + mi * 16) * AS_LD + k16 * 16, AS_LD);
#pragma unroll
            for (int ni = 0; ni < 4; ni++)
                wmma::load_matrix_sync(bf[ni],
                    Bs + (k16 * 16) * BS_LD + wn * 64 + ni * 16, BS_LD);
#pragma unroll
            for (int mi = 0; mi < 2; mi++)
#pragma unroll
                for (int ni = 0; ni < 4; ni++)
                    wmma::mma_sync(acc[mi][ni], af[mi], bf[ni], acc[mi][ni]);
        }
    }

    // ---- ReLU ----
#pragma unroll
    for (int mi = 0; mi < 2; mi++)
#pragma unroll
        for (int ni = 0; ni < 4; ni++)
#pragma unroll
            for (int t = 0; t < acc[mi][ni].num_elements; t++)
                acc[mi][ni].x[t] = fmaxf(acc[mi][ni].x[t], 0.f);

    __syncthreads();

    if (row0 + 128 <= nNodes) {
#pragma unroll
        for (int mi = 0; mi < 2; mi++)
#pragma unroll
            for (int ni = 0; ni < 4; ni++)
                wmma::store_matrix_sync(
                    out + (size_t)(row0 + wm * 32 + mi * 16) * COUT
                        + wn * 64 + ni * 16,
                    acc[mi][ni], COUT, wmma::mem_row_major);
    } else {
        // tail CTA: stage 32-row chunks through float view of smem
        float* stg = reinterpret_cast<float*>(smem);   // 32 x 264 floats (33 KB)
        for (int chunk = 0; chunk < 4; chunk++) {
            __syncthreads();
            if (wm == chunk) {
#pragma unroll
                for (int mi = 0; mi < 2; mi++)
#pragma unroll
                    for (int ni = 0; ni < 4; ni++)
                        wmma::store_matrix_sync(
                            stg + (mi * 16) * 264 + wn * 64 + ni * 16,
                            acc[mi][ni], 264, wmma::mem_row_major);
            }
            __syncthreads();
            int base = row0 + chunk * 32;
            for (int idx = tid; idx < 32 * 256; idx += 512) {
                int r = idx >> 8, c = idx & 255;
                int gr = base + r;
                if (gr < nNodes)
                    out[(size_t)gr * COUT + c] = stg[r * 264 + c];
            }
        }
    }
}

// ---------------------------------------------------------------------------
extern "C" void kernel_launch(void* const* d_in, const int* in_sizes, int n_in,
                              void* d_out, int out_size) {
    const float*  D   = (const float*)d_in[0];
    const int*    row = (const int*)d_in[1];
    const float4* ea  = (const float4*)d_in[2];
    const float*  X   = (const float*)d_in[3];
    const float*  Wp  = (const float*)d_in[4];
    const float*  bp  = (const float*)d_in[5];
    const float*  Ws  = (const float*)d_in[6];
    const float*  bs  = (const float*)d_in[7];
    float* out = (float*)d_out;

    const int nNodes = in_sizes[0];
    const int E      = in_sizes[1];

    static bool attr_set = false;
    if (!attr_set) {
        cudaFuncSetAttribute(gemm_kernel,
                             cudaFuncAttributeMaxDynamicSharedMemorySize,
                             SMEM_BYTES);
        attr_set = true;
    }

    {   // zero + invD
        int n4 = NODES * CE / 4;
        zero_kernel<<<(n4 + 255) / 256, 256>>>(D);
    }
    {   // weights -> half
        int n = KTOT * COUT;
        wtrans_kernel<<<(n + 255) / 256, 256>>>(Wp, Ws);
    }
    {   // X -> half (independent of scatter)
        int n = NODES * CN / 2;
        convx_kernel<<<(n + 255) / 256, 256>>>(X);
    }
    {   // scatter
        int total16 = E * 16;
        scatter_kernel<<<(total16 + 255) / 256, 256>>>(ea, row, total16);
    }
    {   // A/D -> half
        int n = NODES * CE / 2;
        conva_kernel<<<(n + 255) / 256, 256>>>();
    }
    {   // fp16 GEMM
        int grid = (nNodes + 127) / 128;
        gemm_kernel<<<grid, 512, SMEM_BYTES>>>(bp, bs, out, nNodes);
    }
}

// round 11
// speedup vs baseline: 1.7387x; 1.1631x over previous
#include <cuda_runtime.h>
#include <cuda_fp16.h>
#include <mma.h>
#include <cstdint>

#define NODES 50000
#define CE    64
#define CN    256
#define KTOT  320
#define COUT  256
#define KSTEP 32
#define NKS   10   // 320 / 32
#define STAGES 3

#define AS_LD   40                     // halves: 32 + 8 pad
#define BS_LD   264                    // halves: 256 + 8 pad
#define AS_STAGE (128 * AS_LD)
#define BS_STAGE (32 * BS_LD)
#define SMEM_BYTES ((STAGES * AS_STAGE + STAGES * BS_STAGE) * 2)  // 81,408 B

// __device__ scratch
__device__ float  g_invD[NODES];
__device__ __half g_Ah[(size_t)NODES * KTOT];     // half [A/D | X], atomics land in cols [0,64)
__device__ __half g_Bh[KTOT * COUT];              // half weights, k-major

// ---------------------------------------------------------------------------
// cp.async helpers
// ---------------------------------------------------------------------------
__device__ __forceinline__ void cp_async16(void* smem, const void* gsrc, bool pred) {
    uint32_t s = (uint32_t)__cvta_generic_to_shared(smem);
    int sz = pred ? 16 : 0;
    asm volatile("cp.async.cg.shared.global [%0], [%1], 16, %2;\n"
                 :: "r"(s), "l"(gsrc), "r"(sz));
}
#define CP_COMMIT() asm volatile("cp.async.commit_group;\n" ::: "memory")
#define CP_WAIT(n)  asm volatile("cp.async.wait_group %0;\n" :: "n"(n) : "memory")

// ---------------------------------------------------------------------------
// 1) zero A-columns of g_Ah + invD
// ---------------------------------------------------------------------------
__global__ void zero_kernel(const float* __restrict__ D) {
    int i = blockIdx.x * blockDim.x + threadIdx.x;
    if (i < NODES) g_invD[i] = __frcp_rn(__ldg(D + i));
    // zero 64 halves (8 x 16B) per node
    if (i < NODES * 8) {
        int n = i >> 3, c = i & 7;
        *reinterpret_cast<uint4*>(g_Ah + (size_t)n * KTOT + c * 8) =
            make_uint4(0u, 0u, 0u, 0u);
    }
}

// 1b) weights -> half, k-major g_Bh[k][n]
__global__ void wtrans_kernel(const float* __restrict__ Wp,
                              const float* __restrict__ Ws) {
    int idx = blockIdx.x * 256 + threadIdx.x;
    if (idx >= KTOT * COUT) return;
    int k = idx >> 8, n = idx & 255;
    float v = (k < 64) ? __ldg(Wp + k * COUT + n)
                       : __ldg(Ws + (size_t)(k - 64) * COUT + n);
    g_Bh[idx] = __float2half_rn(v);
}

// 1c) X -> half into g_Ah columns [64, 320)
__global__ void convx_kernel(const float* __restrict__ X) {
    int i = blockIdx.x * blockDim.x + threadIdx.x;   // half2 index
    const int tot = NODES * CN / 2;
    if (i >= tot) return;
    int n = i / (CN / 2), c2 = i % (CN / 2);
    float2 v = *reinterpret_cast<const float2*>(X + (size_t)n * CN + c2 * 2);
    *reinterpret_cast<__half2*>(g_Ah + (size_t)n * KTOT + 64 + c2 * 2) =
        __floats2half2_rn(v.x, v.y);
}

// ---------------------------------------------------------------------------
// 2) edge scatter: 8 threads/edge, each reads 32B, scales, packs to 8 halves,
//    one red.global.add.noftz.v4.f16x2 (16B) into g_Ah[row, 0:64).
// ---------------------------------------------------------------------------
__global__ void scatter_kernel(const float4* __restrict__ ea,
                               const int* __restrict__ row_idx, int total8) {
    int i = blockIdx.x * 256 + threadIdx.x;
    if (i >= total8) return;
    int e = i >> 3, t = i & 7;
    int r = __ldg(row_idx + e);
    float s = __ldg(g_invD + r);
    float4 v0 = __ldg(ea + (size_t)e * 16 + t * 2);
    float4 v1 = __ldg(ea + (size_t)e * 16 + t * 2 + 1);
    __half2 h0 = __floats2half2_rn(v0.x * s, v0.y * s);
    __half2 h1 = __floats2half2_rn(v0.z * s, v0.w * s);
    __half2 h2 = __floats2half2_rn(v1.x * s, v1.y * s);
    __half2 h3 = __floats2half2_rn(v1.z * s, v1.w * s);
    __half* dst = g_Ah + (size_t)r * KTOT + t * 8;
    asm volatile("red.global.add.noftz.v4.f16x2 [%0], {%1, %2, %3, %4};"
                 :: "l"(dst),
                    "r"(*reinterpret_cast<uint32_t*>(&h0)),
                    "r"(*reinterpret_cast<uint32_t*>(&h1)),
                    "r"(*reinterpret_cast<uint32_t*>(&h2)),
                    "r"(*reinterpret_cast<uint32_t*>(&h3))
                 : "memory");
}

// ---------------------------------------------------------------------------
// 3) fp16 GEMM  out = relu(g_Ah @ g_Bh + bias)   (unchanged from R10)
// ---------------------------------------------------------------------------
using namespace nvcuda;

__device__ __forceinline__ void load_stage(
    __half* As, __half* Bs, int ks, int row0, int nNodes, int tid)
{
    const int k0 = ks * KSTEP;
    {
        int r  = tid >> 2, c8 = (tid & 3) * 8;
        int gr = row0 + r;
        bool ok = gr < nNodes;
        int grc = ok ? gr : 0;
        cp_async16(As + r * AS_LD + c8,
                   g_Ah + (size_t)grc * KTOT + k0 + c8, ok);
    }
    const __half* bsrc = g_Bh + (size_t)k0 * COUT;
#pragma unroll
    for (int i = 0; i < 2; i++) {
        int j = tid + i * 512;
        int r = j >> 5, c8 = (j & 31) * 8;
        cp_async16(Bs + r * BS_LD + c8, bsrc + r * COUT + c8, true);
    }
}

typedef wmma::fragment<wmma::matrix_a, 16, 16, 16, __half, wmma::row_major> AFrag;
typedef wmma::fragment<wmma::matrix_b, 16, 16, 16, __half, wmma::row_major> BFrag;

__global__ __launch_bounds__(512, 1)
void gemm_kernel(const float* __restrict__ bp, const float* __restrict__ bs,
                 float* __restrict__ out, int nNodes) {
    extern __shared__ __half smem[];
    __half* AsBase = smem;
    __half* BsBase = smem + STAGES * AS_STAGE;

    const int tid  = threadIdx.x;
    const int warp = tid >> 5;
    const int wm   = warp >> 2;
    const int wn   = warp & 3;
    const int row0 = blockIdx.x * 128;

    float* biasf = reinterpret_cast<float*>(smem);   // 16 x 264 floats
    for (int i = tid; i < 16 * 256; i += 512) {
        int r = i >> 8, c = i & 255;
        biasf[r * 264 + c] = __ldg(bp + c) + __ldg(bs + c);
    }
    __syncthreads();

    wmma::fragment<wmma::accumulator, 16, 16, 16, float> acc[2][4];
#pragma unroll
    for (int mi = 0; mi < 2; mi++)
#pragma unroll
        for (int ni = 0; ni < 4; ni++)
            wmma::load_matrix_sync(acc[mi][ni], biasf + wn * 64 + ni * 16,
                                   264, wmma::mem_row_major);
    __syncthreads();

#pragma unroll
    for (int s = 0; s < STAGES - 1; s++) {
        load_stage(AsBase + s * AS_STAGE, BsBase + s * BS_STAGE, s,
                   row0, nNodes, tid);
        CP_COMMIT();
    }

    for (int ks = 0; ks < NKS; ks++) {
        const int cbuf = ks % STAGES;
        const __half* As = AsBase + cbuf * AS_STAGE;
        const __half* Bs = BsBase + cbuf * BS_STAGE;

        if (ks < NKS - 1) { CP_WAIT(1); } else { CP_WAIT(0); }
        __syncthreads();

        if (ks + STAGES - 1 < NKS) {
            const int wbuf = (ks + STAGES - 1) % STAGES;
            load_stage(AsBase + wbuf * AS_STAGE, BsBase + wbuf * BS_STAGE,
                       ks + STAGES - 1, row0, nNodes, tid);
            CP_COMMIT();
        }

#pragma unroll
        for (int k16 = 0; k16 < 2; k16++) {
            AFrag af[2];
            BFrag bf[4];
#pragma unroll
            for (int mi = 0; mi < 2; mi++)
                wmma::load_matrix_sync(af[mi],
                    As + (wm * 32 + mi * 16) * AS_LD + k16 * 16, AS_LD);
#pragma unroll
            for (int ni = 0; ni < 4; ni++)
                wmma::load_matrix_sync(bf[ni],
                    Bs + (k16 * 16) * BS_LD + wn * 64 + ni * 16, BS_LD);
#pragma unroll
            for (int mi = 0; mi < 2; mi++)
#pragma unroll
                for (int ni = 0; ni < 4; ni++)
                    wmma::mma_sync(acc[mi][ni], af[mi], bf[ni], acc[mi][ni]);
        }
    }

#pragma unroll
    for (int mi = 0; mi < 2; mi++)
#pragma unroll
        for (int ni = 0; ni < 4; ni++)
#pragma unroll
            for (int t = 0; t < acc[mi][ni].num_elements; t++)
                acc[mi][ni].x[t] = fmaxf(acc[mi][ni].x[t], 0.f);

    __syncthreads();

    if (row0 + 128 <= nNodes) {
#pragma unroll
        for (int mi = 0; mi < 2; mi++)
#pragma unroll
            for (int ni = 0; ni < 4; ni++)
                wmma::store_matrix_sync(
                    out + (size_t)(row0 + wm * 32 + mi * 16) * COUT
                        + wn * 64 + ni * 16,
                    acc[mi][ni], COUT, wmma::mem_row_major);
    } else {
        float* stg = reinterpret_cast<float*>(smem);   // 32 x 264 floats
        for (int chunk = 0; chunk < 4; chunk++) {
            __syncthreads();
            if (wm == chunk) {
#pragma unroll
                for (int mi = 0; mi < 2; mi++)
#pragma unroll
                    for (int ni = 0; ni < 4; ni++)
                        wmma::store_matrix_sync(
                            stg + (mi * 16) * 264 + wn * 64 + ni * 16,
                            acc[mi][ni], 264, wmma::mem_row_major);
            }
            __syncthreads();
            int base = row0 + chunk * 32;
            for (int idx = tid; idx < 32 * 256; idx += 512) {
                int r = idx >> 8, c = idx & 255;
                int gr = base + r;
                if (gr < nNodes)
                    out[(size_t)gr * COUT + c] = stg[r * 264 + c];
            }
        }
    }
}

// ---------------------------------------------------------------------------
extern "C" void kernel_launch(void* const* d_in, const int* in_sizes, int n_in,
                              void* d_out, int out_size) {
    const float*  D   = (const float*)d_in[0];
    const int*    row = (const int*)d_in[1];
    const float4* ea  = (const float4*)d_in[2];
    const float*  X   = (const float*)d_in[3];
    const float*  Wp  = (const float*)d_in[4];
    const float*  bp  = (const float*)d_in[5];
    const float*  Ws  = (const float*)d_in[6];
    const float*  bs  = (const float*)d_in[7];
    float* out = (float*)d_out;

    const int nNodes = in_sizes[0];
    const int E      = in_sizes[1];

    static bool attr_set = false;
    if (!attr_set) {
        cudaFuncSetAttribute(gemm_kernel,
                             cudaFuncAttributeMaxDynamicSharedMemorySize,
                             SMEM_BYTES);
        attr_set = true;
    }

    {   // zero A-cols + invD
        int n = NODES * 8;
        zero_kernel<<<(n + 255) / 256, 256>>>(D);
    }
    {   // weights -> half
        int n = KTOT * COUT;
        wtrans_kernel<<<(n + 255) / 256, 256>>>(Wp, Ws);
    }
    {   // X -> half
        int n = NODES * CN / 2;
        convx_kernel<<<(n + 255) / 256, 256>>>(X);
    }
    {   // scatter (fp16 atomics)
        int total8 = E * 8;
        scatter_kernel<<<(total8 + 255) / 256, 256>>>(ea, row, total8);
    }
    {   // fp16 GEMM
        int grid = (nNodes + 127) / 128;
        gemm_kernel<<<grid, 512, SMEM_BYTES>>>(bp, bs, out, nNodes);
    }
}